// round 2
// baseline (speedup 1.0000x reference)
#include <cuda_runtime.h>
#include <cstdint>

#define MARGIN 0.3f
#define EPSV   1e-6f

#define MAX_B 8192
#define MAX_L 4096
#define INF_I 0x7fffffff

__device__ int   g_min1[MAX_L];     // first occurrence index per label
__device__ int   g_min2[MAX_L];     // second occurrence index per label
__device__ int   g_diff;            // first index whose label != labels[0]
__device__ int   g_odd_nonzero;     // any nonzero 32-bit word at odd index -> labels are int32
__device__ float g_loss[MAX_B];     // per-anchor triplet loss (0 if invalid)
__device__ int   g_valid[MAX_B];    // per-anchor validity

// Read label i from a buffer whose element type (int32 vs int64) is flagged by is64.
__device__ __forceinline__ int read_label(const void* lab, int i, int is64) {
    if (is64) return (int)((const long long*)lab)[i];
    return ((const int*)lab)[i];
}

// ---------------------------------------------------------------- init + dtype detect
__global__ void k_init(const int* __restrict__ lab32, int B) {
    int t = blockIdx.x * blockDim.x + threadIdx.x;
    if (t < MAX_L) { g_min1[t] = INF_I; g_min2[t] = INF_I; }
    if (t == 0)    { g_diff = INF_I; g_odd_nonzero = 0; }
}

__global__ void k_detect(const int* __restrict__ lab32, int B) {
    // Scan odd 32-bit word indices < B. Safe for both dtypes (int64 buffer has 2B words).
    int i = (blockIdx.x * blockDim.x + threadIdx.x) * 2 + 1;
    if (i < B && lab32[i] != 0) atomicOr(&g_odd_nonzero, 1);
}

// ---------------------------------------------------------------- pass 1
__global__ void k_pass1(const void* __restrict__ labels, int B) {
    int is64 = (g_odd_nonzero == 0);
    int i = blockIdx.x * blockDim.x + threadIdx.x;
    if (i >= B) return;
    int li = read_label(labels, i, is64);
    if (li >= 0 && li < MAX_L) atomicMin(&g_min1[li], i);
    if (li != read_label(labels, 0, is64)) atomicMin(&g_diff, i);
}

// ---------------------------------------------------------------- pass 2
__global__ void k_pass2(const void* __restrict__ labels, int B) {
    int is64 = (g_odd_nonzero == 0);
    int i = blockIdx.x * blockDim.x + threadIdx.x;
    if (i >= B) return;
    int l = read_label(labels, i, is64);
    if (l < 0 || l >= MAX_L) return;
    if (g_min1[l] != i) atomicMin(&g_min2[l], i);
}

// ---------------------------------------------------------------- main: warp per anchor
__global__ void k_dist(const float* __restrict__ features,
                       const void* __restrict__ labels,
                       int B, int D) {
    int warp = (blockIdx.x * blockDim.x + threadIdx.x) >> 5;
    int lane = threadIdx.x & 31;
    if (warp >= B) return;
    int i = warp;
    int is64 = (g_odd_nonzero == 0);

    int li = read_label(labels, i, is64);
    int l0 = read_label(labels, 0, is64);

    int p = (li >= 0 && li < MAX_L) ? g_min1[li] : INF_I;
    if (p == i && li >= 0 && li < MAX_L) p = g_min2[li];
    int n = (li != l0) ? 0 : g_diff;

    bool valid = (p != INF_I) && (n != INF_I);
    if (!valid) {
        if (lane == 0) { g_loss[i] = 0.0f; g_valid[i] = 0; }
        return;
    }

    const float4* __restrict__ A = (const float4*)(features + (size_t)i * D);
    const float4* __restrict__ P = (const float4*)(features + (size_t)p * D);
    const float4* __restrict__ N = (const float4*)(features + (size_t)n * D);
    int nv = D >> 2;

    float sap = 0.0f, san = 0.0f;
    for (int k = lane; k < nv; k += 32) {
        float4 a  = A[k];
        float4 pp = P[k];
        float4 nn = N[k];
        float d;
        d = a.x - pp.x + EPSV; sap = fmaf(d, d, sap);
        d = a.y - pp.y + EPSV; sap = fmaf(d, d, sap);
        d = a.z - pp.z + EPSV; sap = fmaf(d, d, sap);
        d = a.w - pp.w + EPSV; sap = fmaf(d, d, sap);
        d = a.x - nn.x + EPSV; san = fmaf(d, d, san);
        d = a.y - nn.y + EPSV; san = fmaf(d, d, san);
        d = a.z - nn.z + EPSV; san = fmaf(d, d, san);
        d = a.w - nn.w + EPSV; san = fmaf(d, d, san);
    }
    #pragma unroll
    for (int off = 16; off > 0; off >>= 1) {
        sap += __shfl_down_sync(0xffffffffu, sap, off);
        san += __shfl_down_sync(0xffffffffu, san, off);
    }
    if (lane == 0) {
        float dap = sqrtf(sap);
        float dan = sqrtf(san);
        g_loss[i]  = fmaxf(dap - dan + MARGIN, 0.0f);
        g_valid[i] = 1;
    }
}

// ---------------------------------------------------------------- deterministic reduce
__global__ void k_reduce(float* __restrict__ out, int B) {
    __shared__ float s_sum[1024];
    __shared__ int   s_cnt[1024];
    int t = threadIdx.x;
    float sum = 0.0f;
    int cnt = 0;
    for (int i = t; i < B; i += 1024) {
        sum += g_loss[i];
        cnt += g_valid[i];
    }
    s_sum[t] = sum;
    s_cnt[t] = cnt;
    __syncthreads();
    for (int off = 512; off > 0; off >>= 1) {
        if (t < off) {
            s_sum[t] += s_sum[t + off];
            s_cnt[t] += s_cnt[t + off];
        }
        __syncthreads();
    }
    if (t == 0) {
        int c = s_cnt[0];
        out[0] = (c > 0) ? (s_sum[0] / (float)c) : 0.0f;
    }
}

// ---------------------------------------------------------------- launch
extern "C" void kernel_launch(void* const* d_in, const int* in_sizes, int n_in,
                              void* d_out, int out_size) {
    // Robust input identification: features = the larger buffer.
    int i_feat = (in_sizes[0] >= in_sizes[1]) ? 0 : 1;
    int i_lab  = 1 - i_feat;
    const float* features = (const float*)d_in[i_feat];
    const void*  labels   = d_in[i_lab];
    int B = in_sizes[i_lab];
    int D = in_sizes[i_feat] / B;

    k_init  <<<(MAX_L + 1023) / 1024, 1024>>>((const int*)labels, B);
    k_detect<<<(B / 2 + 255) / 256, 256>>>((const int*)labels, B);
    k_pass1 <<<(B + 255) / 256, 256>>>(labels, B);
    k_pass2 <<<(B + 255) / 256, 256>>>(labels, B);
    k_dist  <<<(B + 7) / 8, 256>>>(features, labels, B, D);
    k_reduce<<<1, 1024>>>((float*)d_out, B);
}